// round 3
// baseline (speedup 1.0000x reference)
#include <cuda_runtime.h>
#include <cuda_bf16.h>
#include <math.h>

// Problem constants (fixed by the dataset)
#define NN 100000
#define EE 3200000
#define KK 1024

// ---------------- scratch (device globals; no allocation allowed) -----------
__device__ __align__(16) float g_x12[NN * 12];   // x padded to 12 cols
__device__ __align__(16) float g_aggx[NN * 12];  // layer-1 aggregation in input space
__device__ int           g_deg[NN];
__device__ float         g_dis[NN];
__device__ float         g_h2[NN];               // per-node scalar (x_input @ W2)
__device__ float         g_agg2[NN];             // layer-2 aggregation (only ready nodes)
__device__ unsigned char g_flag[NN];             // ready-node membership
__device__ float         g_msum[64];             // sum of relu(h1) for mean

// vector reduction: red.global.add.v4.f32 (sm_90+)
__device__ __forceinline__ void red_add_v4(float* addr, float4 v) {
    asm volatile("red.global.add.v4.f32 [%0], {%1,%2,%3,%4};"
                 :: "l"(addr), "f"(v.x), "f"(v.y), "f"(v.z), "f"(v.w)
                 : "memory");
}

// ---------------- kernels ---------------------------------------------------

__global__ void k_zero(int n) {
    int idx = blockIdx.x * blockDim.x + threadIdx.x;
    int stride = gridDim.x * blockDim.x;
    for (int j = idx; j < n * 12; j += stride) g_aggx[j] = 0.f;
    for (int j = idx; j < n; j += stride) {
        g_deg[j] = 0;
        g_agg2[j] = 0.f;
        g_flag[j] = 0;
    }
    if (idx < 64) g_msum[idx] = 0.f;
}

__global__ void k_x12(const float* __restrict__ x, int n) {
    int idx = blockIdx.x * blockDim.x + threadIdx.x;
    int stride = gridDim.x * blockDim.x;
    for (int j = idx; j < n * 12; j += stride) {
        int i = j / 12, d = j % 12;
        g_x12[j] = (d < 11) ? x[i * 11 + d] : 0.f;
    }
}

__global__ void k_flags(const int* __restrict__ ridx, int k) {
    int t = blockIdx.x * blockDim.x + threadIdx.x;
    if (t < k) g_flag[ridx[t]] = 1;
}

__global__ void k_deg(const int* __restrict__ src, int e) {
    int idx = blockIdx.x * blockDim.x + threadIdx.x;
    int stride = gridDim.x * blockDim.x;
    for (int j = idx; j < e; j += stride)
        atomicAdd(&g_deg[src[j]], 1);
}

__global__ void k_dis(int n) {
    int i = blockIdx.x * blockDim.x + threadIdx.x;
    if (i < n) g_dis[i] = rsqrtf((float)(g_deg[i] + 1));
}

// Main edge pass: agg_x[src] += dis[dst] * x12[dst]   (12 floats = 3 x red.v4)
__global__ void k_agg(const int* __restrict__ src, const int* __restrict__ dst, int e) {
    int idx = blockIdx.x * blockDim.x + threadIdx.x;
    int stride = gridDim.x * blockDim.x;
    for (int j = idx; j < e; j += stride) {
        int s = src[j];
        int d = dst[j];
        float w = __ldg(&g_dis[d]);
        const float4* xr = (const float4*)&g_x12[d * 12];
        float4 a = xr[0], b = xr[1], c = xr[2];
        a.x *= w; a.y *= w; a.z *= w; a.w *= w;
        b.x *= w; b.y *= w; b.z *= w; b.w *= w;
        c.x *= w; c.y *= w; c.z *= w; c.w *= w;
        float* p = &g_aggx[s * 12];
        red_add_v4(p, a);
        red_add_v4(p + 4, b);
        red_add_v4(p + 8, c);
    }
}

// Node pass: warp per node. z = dis*agg + dis^2*x ; h1 = relu(z@W1+b1) in regs;
// accumulate mean-sum; h2 = h1 . W2[:64] + x . W2[64:75]
__global__ void k_node(const float* __restrict__ W1, const float* __restrict__ b1,
                       const float* __restrict__ W2, int n) {
    int gw = (blockIdx.x * blockDim.x + threadIdx.x) >> 5;
    int lane = threadIdx.x & 31;
    int nwarp = (gridDim.x * blockDim.x) >> 5;

    float w1c0[11], w1c1[11];
#pragma unroll
    for (int d = 0; d < 11; d++) {
        w1c0[d] = __ldg(&W1[d * 64 + lane]);
        w1c1[d] = __ldg(&W1[d * 64 + lane + 32]);
    }
    float bb0 = __ldg(&b1[lane]);
    float bb1 = __ldg(&b1[lane + 32]);
    float w2a = __ldg(&W2[lane]);
    float w2b = __ldg(&W2[lane + 32]);
    float w2x[11];
#pragma unroll
    for (int d = 0; d < 11; d++) w2x[d] = __ldg(&W2[64 + d]);

    float m0 = 0.f, m1 = 0.f;

    for (int i = gw; i < n; i += nwarp) {
        float di = g_dis[i];
        float di2 = di * di;
        const float4* ar = (const float4*)&g_aggx[i * 12];
        const float4* xr = (const float4*)&g_x12[i * 12];
        float4 a0 = ar[0], a1 = ar[1], a2 = ar[2];
        float4 x0 = xr[0], x1 = xr[1], x2 = xr[2];

        float z[11];
        z[0]  = di * a0.x + di2 * x0.x;
        z[1]  = di * a0.y + di2 * x0.y;
        z[2]  = di * a0.z + di2 * x0.z;
        z[3]  = di * a0.w + di2 * x0.w;
        z[4]  = di * a1.x + di2 * x1.x;
        z[5]  = di * a1.y + di2 * x1.y;
        z[6]  = di * a1.z + di2 * x1.z;
        z[7]  = di * a1.w + di2 * x1.w;
        z[8]  = di * a2.x + di2 * x2.x;
        z[9]  = di * a2.y + di2 * x2.y;
        z[10] = di * a2.z + di2 * x2.z;

        float acc0 = bb0, acc1 = bb1;
#pragma unroll
        for (int d = 0; d < 11; d++) {
            acc0 = fmaf(z[d], w1c0[d], acc0);
            acc1 = fmaf(z[d], w1c1[d], acc1);
        }
        float h0 = fmaxf(acc0, 0.f);
        float h1 = fmaxf(acc1, 0.f);
        m0 += h0;
        m1 += h1;

        float p = h0 * w2a + h1 * w2b;
#pragma unroll
        for (int off = 16; off; off >>= 1)
            p += __shfl_xor_sync(0xffffffffu, p, off);

        if (lane == 0) {
            float xv[11] = {x0.x, x0.y, x0.z, x0.w, x1.x, x1.y, x1.z, x1.w,
                            x2.x, x2.y, x2.z};
            float xa = 0.f;
#pragma unroll
            for (int d = 0; d < 11; d++) xa = fmaf(xv[d], w2x[d], xa);
            g_h2[i] = p + xa;
        }
    }
    atomicAdd(&g_msum[lane], m0);
    atomicAdd(&g_msum[lane + 32], m1);
}

// Layer-2 edge pass: only edges whose src is a ready node do work (~1%)
__global__ void k_edge2(const int* __restrict__ src, const int* __restrict__ dst, int e) {
    int idx = blockIdx.x * blockDim.x + threadIdx.x;
    int stride = gridDim.x * blockDim.x;
    for (int j = idx; j < e; j += stride) {
        int s = src[j];
        if (g_flag[s]) {
            int d = dst[j];
            atomicAdd(&g_agg2[s], g_dis[d] * g_h2[d]);
        }
    }
}

// Readout: x_mean, v, prob_nothing, logits at ready_idx, softmax. 1 block.
__global__ void k_final(const int* __restrict__ ridx,
                        const float* __restrict__ b2,
                        const float* __restrict__ Wd, const float* __restrict__ bd,
                        const float* __restrict__ Wv, const float* __restrict__ bv,
                        int k, int n, float* __restrict__ out) {
    __shared__ float s_log[KK + 1];
    __shared__ float s_red[1024];
    __shared__ float s_xm[64];
    __shared__ float s_v, s_pn;
    int t = threadIdx.x;

    if (t < 64) s_xm[t] = g_msum[t] / (float)n;
    __syncthreads();

    if (t == 0) {
        float v = 0.f, pn = 0.f;
        for (int j = 0; j < 64; j++) {
            v = fmaf(s_xm[j], Wv[j], v);
            pn = fmaf(s_xm[j], Wd[j], pn);
        }
        s_v = v + bv[0];
        s_pn = pn + bd[0];
    }
    __syncthreads();

    float bb2 = b2[0];
    for (int i = t; i <= k; i += blockDim.x) {
        float l;
        if (i < k) {
            int r = ridx[i];
            float di = g_dis[r];
            l = di * g_agg2[r] + di * di * g_h2[r] + bb2;
        } else {
            l = s_pn;
        }
        s_log[i] = l;
    }
    __syncthreads();

    // max reduce
    float m = -1e30f;
    for (int i = t; i <= k; i += blockDim.x) m = fmaxf(m, s_log[i]);
    s_red[t] = m;
    __syncthreads();
    for (int s = 512; s; s >>= 1) {
        if (t < s) s_red[t] = fmaxf(s_red[t], s_red[t + s]);
        __syncthreads();
    }
    float mx = s_red[0];
    __syncthreads();

    // sum reduce
    float sum = 0.f;
    for (int i = t; i <= k; i += blockDim.x) sum += expf(s_log[i] - mx);
    s_red[t] = sum;
    __syncthreads();
    for (int s = 512; s; s >>= 1) {
        if (t < s) s_red[t] += s_red[t + s];
        __syncthreads();
    }
    float inv = 1.0f / s_red[0];

    for (int i = t; i <= k; i += blockDim.x)
        out[i] = expf(s_log[i] - mx) * inv;
    if (t == 0) out[k + 1] = s_v;
}

// ---------------- launch -----------------------------------------------------

extern "C" void kernel_launch(void* const* d_in, const int* in_sizes, int n_in,
                              void* d_out, int out_size) {
    const float* x   = (const float*)d_in[0];
    const int*   ei  = (const int*)d_in[1];
    const int*   rid = (const int*)d_in[2];
    const float* W1  = (const float*)d_in[3];
    const float* b1  = (const float*)d_in[4];
    const float* W2  = (const float*)d_in[5];
    const float* b2  = (const float*)d_in[6];
    const float* Wd  = (const float*)d_in[7];
    const float* bd  = (const float*)d_in[8];
    const float* Wv  = (const float*)d_in[9];
    const float* bv  = (const float*)d_in[10];

    int n = in_sizes[0] / 11;
    int e = in_sizes[1] / 2;
    int k = in_sizes[2];
    if (n > NN) n = NN;
    if (e > EE) e = EE;
    if (k > KK) k = KK;

    const int* src = ei;
    const int* dst = ei + e;

    k_zero<<<2048, 256>>>(n);
    k_x12<<<(n * 12 + 255) / 256, 256>>>(x, n);
    k_flags<<<(k + 255) / 256, 256>>>(rid, k);
    k_deg<<<(e + 255) / 256, 256>>>(src, e);
    k_dis<<<(n + 255) / 256, 256>>>(n);
    k_agg<<<(e + 255) / 256, 256>>>(src, dst, e);
    k_node<<<1480, 256>>>(W1, b1, W2, n);
    k_edge2<<<(e + 255) / 256, 256>>>(src, dst, e);
    k_final<<<1, 1024>>>(rid, b2, Wd, bd, Wv, bv, k, n, (float*)d_out);
}

// round 4
// speedup vs baseline: 1.0119x; 1.0119x over previous
#include <cuda_runtime.h>
#include <cuda_bf16.h>
#include <math.h>

// Problem constants (fixed by the dataset)
#define NN 100000
#define EE 3200000
#define KK 1024

// ---------------- scratch (device globals; no allocation allowed) -----------
__device__ __align__(16) float g_x12[NN * 12];   // x padded to 12 cols
__device__ __align__(16) float g_y12[NN * 12];   // dis[i] * x12  (pre-scaled gather table)
__device__ __align__(16) float g_aggx[NN * 12];  // layer-1 aggregation in input space
__device__ int           g_deg[NN];
__device__ float         g_dis[NN];
__device__ float         g_hd[NN];               // dis[i] * (x_input[i] @ W2)
__device__ float         g_agg2[NN];             // layer-2 aggregation (ready rows only)
__device__ unsigned char g_flag[NN];             // ready-node membership
__device__ float         g_msum[64];             // sum of relu(h1) for the mean
__device__ int           g_elist[EE];            // compacted edge ids with ready src
__device__ int           g_cnt;                  // count of compacted edges

// vector reduction: red.global.add.v4.f32 (sm_90+)
__device__ __forceinline__ void red_add_v4(float* addr, float4 v) {
    asm volatile("red.global.add.v4.f32 [%0], {%1,%2,%3,%4};"
                 :: "l"(addr), "f"(v.x), "f"(v.y), "f"(v.z), "f"(v.w)
                 : "memory");
}

// ---------------- kernels ---------------------------------------------------

// One fused init: pad x -> x12, zero aggx/deg/agg2/msum/cnt, set ready flags.
// g_flag is never re-zeroed: inputs are identical across graph replays, so the
// set of flags written is identical (idempotent) every call.
__global__ void k_init(const float* __restrict__ x, const int* __restrict__ ridx,
                       int n, int k) {
    int idx = blockIdx.x * blockDim.x + threadIdx.x;
    int stride = gridDim.x * blockDim.x;
    for (int j = idx; j < n * 12; j += stride) {
        int i = j / 12, d = j % 12;
        g_x12[j] = (d < 11) ? x[i * 11 + d] : 0.f;
        g_aggx[j] = 0.f;
    }
    for (int j = idx; j < n; j += stride) {
        g_deg[j] = 0;
        g_agg2[j] = 0.f;
    }
    for (int j = idx; j < k; j += stride) g_flag[ridx[j]] = 1;
    if (idx < 64) g_msum[idx] = 0.f;
    if (idx == 0) g_cnt = 0;
}

// Degree count (int RED) + compact the ready-src edge list in the same pass.
// 4 edges per thread via int4.
__global__ void k_deg(const int* __restrict__ src, int e) {
    int j4 = blockIdx.x * blockDim.x + threadIdx.x;
    int e4 = e >> 2;
    if (j4 < e4) {
        int4 s = ((const int4*)src)[j4];
        atomicAdd(&g_deg[s.x], 1);
        atomicAdd(&g_deg[s.y], 1);
        atomicAdd(&g_deg[s.z], 1);
        atomicAdd(&g_deg[s.w], 1);
        int base = j4 << 2;
        if (g_flag[s.x]) g_elist[atomicAdd(&g_cnt, 1)] = base;
        if (g_flag[s.y]) g_elist[atomicAdd(&g_cnt, 1)] = base + 1;
        if (g_flag[s.z]) g_elist[atomicAdd(&g_cnt, 1)] = base + 2;
        if (g_flag[s.w]) g_elist[atomicAdd(&g_cnt, 1)] = base + 3;
    }
    if (j4 == 0) {  // tail (e % 4), usually empty
        for (int j = e4 << 2; j < e; j++) {
            int s = src[j];
            atomicAdd(&g_deg[s], 1);
            if (g_flag[s]) g_elist[atomicAdd(&g_cnt, 1)] = j;
        }
    }
}

// dis = rsqrt(deg+1); pre-scale gather table y12 = dis * x12
__global__ void k_disy(int n) {
    int i = blockIdx.x * blockDim.x + threadIdx.x;
    if (i < n) {
        float dis = rsqrtf((float)(g_deg[i] + 1));
        g_dis[i] = dis;
        const float4* xr = (const float4*)&g_x12[i * 12];
        float4* yr = (float4*)&g_y12[i * 12];
#pragma unroll
        for (int q = 0; q < 3; q++) {
            float4 v = xr[q];
            v.x *= dis; v.y *= dis; v.z *= dis; v.w *= dis;
            yr[q] = v;
        }
    }
}

// Main edge pass: aggx[src] += y12[dst]. 4 edges/thread; all 12 gather loads
// issued before the 12 REDs for max MLP. No per-edge dis work.
__global__ void k_agg(const int* __restrict__ src, const int* __restrict__ dst, int e) {
    int j4 = blockIdx.x * blockDim.x + threadIdx.x;
    int e4 = e >> 2;
    if (j4 < e4) {
        int4 s = ((const int4*)src)[j4];
        int4 d = ((const int4*)dst)[j4];
        const float4* y0 = (const float4*)&g_y12[d.x * 12];
        const float4* y1 = (const float4*)&g_y12[d.y * 12];
        const float4* y2 = (const float4*)&g_y12[d.z * 12];
        const float4* y3 = (const float4*)&g_y12[d.w * 12];
        float4 a0 = y0[0], a1 = y0[1], a2 = y0[2];
        float4 b0 = y1[0], b1 = y1[1], b2 = y1[2];
        float4 c0 = y2[0], c1 = y2[1], c2 = y2[2];
        float4 e0 = y3[0], e1 = y3[1], e2 = y3[2];
        float* p0 = &g_aggx[s.x * 12];
        float* p1 = &g_aggx[s.y * 12];
        float* p2 = &g_aggx[s.z * 12];
        float* p3 = &g_aggx[s.w * 12];
        red_add_v4(p0, a0); red_add_v4(p0 + 4, a1); red_add_v4(p0 + 8, a2);
        red_add_v4(p1, b0); red_add_v4(p1 + 4, b1); red_add_v4(p1 + 8, b2);
        red_add_v4(p2, c0); red_add_v4(p2 + 4, c1); red_add_v4(p2 + 8, c2);
        red_add_v4(p3, e0); red_add_v4(p3 + 4, e1); red_add_v4(p3 + 8, e2);
    }
    if (j4 == 0) {  // tail
        for (int j = e4 << 2; j < e; j++) {
            int s = src[j], d = dst[j];
            const float4* yr = (const float4*)&g_y12[d * 12];
            float* p = &g_aggx[s * 12];
            red_add_v4(p, yr[0]); red_add_v4(p + 4, yr[1]); red_add_v4(p + 8, yr[2]);
        }
    }
}

// Node pass (warp/node): z = dis*(agg + y); h1 = relu(z@W1+b1) in regs;
// accumulate mean-sum; hd = dis * (h1.W2[:64] + x.W2[64:75])
__global__ void k_node(const float* __restrict__ W1, const float* __restrict__ b1,
                       const float* __restrict__ W2, int n) {
    int gw = (blockIdx.x * blockDim.x + threadIdx.x) >> 5;
    int lane = threadIdx.x & 31;
    int nwarp = (gridDim.x * blockDim.x) >> 5;

    float w1c0[11], w1c1[11];
#pragma unroll
    for (int d = 0; d < 11; d++) {
        w1c0[d] = __ldg(&W1[d * 64 + lane]);
        w1c1[d] = __ldg(&W1[d * 64 + lane + 32]);
    }
    float bb0 = __ldg(&b1[lane]);
    float bb1 = __ldg(&b1[lane + 32]);
    float w2a = __ldg(&W2[lane]);
    float w2b = __ldg(&W2[lane + 32]);
    float w2x[11];
#pragma unroll
    for (int d = 0; d < 11; d++) w2x[d] = __ldg(&W2[64 + d]);

    float m0 = 0.f, m1 = 0.f;

    for (int i = gw; i < n; i += nwarp) {
        float di = g_dis[i];
        const float4* ar = (const float4*)&g_aggx[i * 12];
        const float4* yr = (const float4*)&g_y12[i * 12];
        const float4* xr = (const float4*)&g_x12[i * 12];
        float4 a0 = ar[0], a1 = ar[1], a2 = ar[2];
        float4 y0 = yr[0], y1 = yr[1], y2 = yr[2];
        float4 x0 = xr[0], x1 = xr[1], x2 = xr[2];

        float z[11];
        z[0]  = di * (a0.x + y0.x);
        z[1]  = di * (a0.y + y0.y);
        z[2]  = di * (a0.z + y0.z);
        z[3]  = di * (a0.w + y0.w);
        z[4]  = di * (a1.x + y1.x);
        z[5]  = di * (a1.y + y1.y);
        z[6]  = di * (a1.z + y1.z);
        z[7]  = di * (a1.w + y1.w);
        z[8]  = di * (a2.x + y2.x);
        z[9]  = di * (a2.y + y2.y);
        z[10] = di * (a2.z + y2.z);

        float acc0 = bb0, acc1 = bb1;
#pragma unroll
        for (int d = 0; d < 11; d++) {
            acc0 = fmaf(z[d], w1c0[d], acc0);
            acc1 = fmaf(z[d], w1c1[d], acc1);
        }
        float h0 = fmaxf(acc0, 0.f);
        float h1 = fmaxf(acc1, 0.f);
        m0 += h0;
        m1 += h1;

        float p = h0 * w2a + h1 * w2b;
#pragma unroll
        for (int off = 16; off; off >>= 1)
            p += __shfl_xor_sync(0xffffffffu, p, off);

        if (lane == 0) {
            float xv[11] = {x0.x, x0.y, x0.z, x0.w, x1.x, x1.y, x1.z, x1.w,
                            x2.x, x2.y, x2.z};
            float xa = 0.f;
#pragma unroll
            for (int d = 0; d < 11; d++) xa = fmaf(xv[d], w2x[d], xa);
            g_hd[i] = di * (p + xa);
        }
    }
    atomicAdd(&g_msum[lane], m0);
    atomicAdd(&g_msum[lane + 32], m1);
}

// Layer-2 edge pass over the compacted (~1%) edge list only.
__global__ void k_edge2(const int* __restrict__ src, const int* __restrict__ dst) {
    int m = g_cnt;
    int idx = blockIdx.x * blockDim.x + threadIdx.x;
    int stride = gridDim.x * blockDim.x;
    for (int i = idx; i < m; i += stride) {
        int j = g_elist[i];
        atomicAdd(&g_agg2[src[j]], g_hd[dst[j]]);
    }
}

// Readout: x_mean, v, prob_nothing, logits at ready_idx, softmax. One block.
__global__ void k_final(const int* __restrict__ ridx,
                        const float* __restrict__ b2,
                        const float* __restrict__ Wd, const float* __restrict__ bd,
                        const float* __restrict__ Wv, const float* __restrict__ bv,
                        int k, int n, float* __restrict__ out) {
    __shared__ float s_log[KK + 1];
    __shared__ float s_red[1024];
    __shared__ float s_xm[64];
    __shared__ float s_v, s_pn;
    int t = threadIdx.x;

    if (t < 64) s_xm[t] = g_msum[t] / (float)n;
    __syncthreads();

    if (t == 0) {
        float v = 0.f, pn = 0.f;
        for (int j = 0; j < 64; j++) {
            v = fmaf(s_xm[j], Wv[j], v);
            pn = fmaf(s_xm[j], Wd[j], pn);
        }
        s_v = v + bv[0];
        s_pn = pn + bd[0];
    }
    __syncthreads();

    float bb2 = b2[0];
    for (int i = t; i <= k; i += blockDim.x) {
        float l;
        if (i < k) {
            int r = ridx[i];
            l = g_dis[r] * (g_agg2[r] + g_hd[r]) + bb2;
        } else {
            l = s_pn;
        }
        s_log[i] = l;
    }
    __syncthreads();

    // max reduce
    float m = -1e30f;
    for (int i = t; i <= k; i += blockDim.x) m = fmaxf(m, s_log[i]);
    s_red[t] = m;
    __syncthreads();
    for (int s = 512; s; s >>= 1) {
        if (t < s) s_red[t] = fmaxf(s_red[t], s_red[t + s]);
        __syncthreads();
    }
    float mx = s_red[0];
    __syncthreads();

    // sum reduce
    float sum = 0.f;
    for (int i = t; i <= k; i += blockDim.x) sum += expf(s_log[i] - mx);
    s_red[t] = sum;
    __syncthreads();
    for (int s = 512; s; s >>= 1) {
        if (t < s) s_red[t] += s_red[t + s];
        __syncthreads();
    }
    float inv = 1.0f / s_red[0];

    for (int i = t; i <= k; i += blockDim.x)
        out[i] = expf(s_log[i] - mx) * inv;
    if (t == 0) out[k + 1] = s_v;
}

// ---------------- launch -----------------------------------------------------

extern "C" void kernel_launch(void* const* d_in, const int* in_sizes, int n_in,
                              void* d_out, int out_size) {
    const float* x   = (const float*)d_in[0];
    const int*   ei  = (const int*)d_in[1];
    const int*   rid = (const int*)d_in[2];
    const float* W1  = (const float*)d_in[3];
    const float* b1  = (const float*)d_in[4];
    const float* W2  = (const float*)d_in[5];
    const float* b2  = (const float*)d_in[6];
    const float* Wd  = (const float*)d_in[7];
    const float* bd  = (const float*)d_in[8];
    const float* Wv  = (const float*)d_in[9];
    const float* bv  = (const float*)d_in[10];

    int n = in_sizes[0] / 11;
    int e = in_sizes[1] / 2;
    int k = in_sizes[2];
    if (n > NN) n = NN;
    if (e > EE) e = EE;
    if (k > KK) k = KK;

    const int* src = ei;
    const int* dst = ei + e;

    int e4 = e >> 2;

    k_init<<<2368, 256>>>(x, rid, n, k);
    k_deg<<<(e4 + 255) / 256, 256>>>(src, e);
    k_disy<<<(n + 255) / 256, 256>>>(n);
    k_agg<<<(e4 + 255) / 256, 256>>>(src, dst, e);
    k_node<<<1480, 256>>>(W1, b1, W2, n);
    k_edge2<<<256, 256>>>(src, dst);
    k_final<<<1, 1024>>>(rid, b2, Wd, bd, Wv, bv, k, n, (float*)d_out);
}

// round 5
// speedup vs baseline: 1.0996x; 1.0867x over previous
#include <cuda_runtime.h>
#include <cuda_bf16.h>
#include <math.h>

// Problem constants (fixed by the dataset)
#define NN 100000
#define EE 3200000
#define KK 1024
#define SLOTS 128          // max degree capacity (Poisson(32): P(deg>=128) ~ 0)
#define NSH 64             // shards for layer-2 edge compaction
#define SHCAP 32768        // per-shard capacity (expected ~512 entries)

// ---------------- scratch (device globals; no allocation allowed) -----------
__device__ __align__(16) float g_x12[NN * 12];   // x padded to 12 cols
__device__ __align__(16) float g_y12[NN * 12];   // dis[i] * x12 (gather table)
__device__ __align__(16) float g_aggx[NN * 12];  // layer-1 aggregation result
__device__ int   g_cnt1[NN];          // bits 0-23: degree counter; bit 24: ready flag
__device__ float g_dis[NN];
__device__ float g_hd[NN];            // dis[i] * (x_input[i] @ W2)
__device__ float g_agg2[NN];          // layer-2 aggregation (ready rows only)
__device__ float g_msum[64];          // sum of relu(h1) for the mean
__device__ int   g_bucket[SLOTS * NN];// transposed CSR: bucket[slot*NN + node] = dst
__device__ int2  g_e2[NSH * SHCAP];   // compacted (src,dst) pairs with ready src
__device__ int   g_shcnt[NSH];

// ---------------- kernels ---------------------------------------------------

// Fused init: pad x -> x12, zero counters. No aggx zeroing (gather overwrites).
__global__ void k_init(const float* __restrict__ x, int n) {
    int idx = blockIdx.x * blockDim.x + threadIdx.x;
    int stride = gridDim.x * blockDim.x;
    for (int j = idx; j < n * 12; j += stride) {
        int i = j / 12, d = j % 12;
        g_x12[j] = (d < 11) ? x[i * 11 + d] : 0.f;
    }
    for (int j = idx; j < n; j += stride) {
        g_cnt1[j] = 0;
        g_agg2[j] = 0.f;
    }
    if (idx < 64) g_msum[idx] = 0.f;
    if (idx < NSH) g_shcnt[idx] = 0;
}

// Seed ready flags into bit 24 of the degree counters (separate launch for ordering).
__global__ void k_ready(const int* __restrict__ ridx, int k) {
    int t = blockIdx.x * blockDim.x + threadIdx.x;
    if (t < k) atomicOr(&g_cnt1[ridx[t]], 1 << 24);
}

// One atomic per edge: counts degree, assigns CSR slot, and (via bit 24)
// compacts ready-src edges into sharded lists. Bucket is [slot][node] so the
// gather pass reads coalesced.
__device__ __forceinline__ void scat(int s, int d, int sh) {
    int old = atomicAdd(&g_cnt1[s], 1);
    g_bucket[(old & 0xFFFFFF) * NN + s] = d;
    if (old & (1 << 24)) {
        int p = atomicAdd(&g_shcnt[sh], 1);
        if (p < SHCAP) g_e2[sh * SHCAP + p] = make_int2(s, d);
    }
}

__global__ void k_scatter(const int* __restrict__ src, const int* __restrict__ dst, int e) {
    int j4 = blockIdx.x * blockDim.x + threadIdx.x;
    int e4 = e >> 2;
    int sh = blockIdx.x & (NSH - 1);
    if (j4 < e4) {
        int4 s = ((const int4*)src)[j4];
        int4 d = ((const int4*)dst)[j4];
        scat(s.x, d.x, sh);
        scat(s.y, d.y, sh);
        scat(s.z, d.z, sh);
        scat(s.w, d.w, sh);
    }
    if (j4 == 0) {  // tail (e % 4)
        for (int j = e4 << 2; j < e; j++) scat(src[j], dst[j], 0);
    }
}

// dis = rsqrt(deg+1); pre-scaled gather table y12 = dis * x12.
__global__ void k_disy(int n) {
    int i = blockIdx.x * blockDim.x + threadIdx.x;
    if (i < n) {
        int deg = g_cnt1[i] & 0xFFFFFF;
        float dis = rsqrtf((float)(deg + 1));
        g_dis[i] = dis;
        const float4* xr = (const float4*)&g_x12[i * 12];
        float4* yr = (float4*)&g_y12[i * 12];
#pragma unroll
        for (int q = 0; q < 3; q++) {
            float4 v = xr[q];
            v.x *= dis; v.y *= dis; v.z *= dis; v.w *= dis;
            yr[q] = v;
        }
    }
}

// Gather-aggregate: thread per node, NO atomics. Sum y12[dst] over the node's
// bucket entries (coalesced bucket reads), one coalesced 48B store.
__global__ void k_gather(int n) {
    int i = blockIdx.x * blockDim.x + threadIdx.x;
    if (i >= n) return;
    int deg = g_cnt1[i] & 0xFFFFFF;

    float4 a0 = {0.f, 0.f, 0.f, 0.f}, a1 = a0, a2 = a0;
    int k = 0;
    for (; k + 2 <= deg; k += 2) {
        int d0 = g_bucket[k * NN + i];
        int d1 = g_bucket[(k + 1) * NN + i];
        const float4* r0 = (const float4*)&g_y12[d0 * 12];
        const float4* r1 = (const float4*)&g_y12[d1 * 12];
        float4 u0 = r0[0], u1 = r0[1], u2 = r0[2];
        float4 v0 = r1[0], v1 = r1[1], v2 = r1[2];
        a0.x += u0.x + v0.x; a0.y += u0.y + v0.y; a0.z += u0.z + v0.z; a0.w += u0.w + v0.w;
        a1.x += u1.x + v1.x; a1.y += u1.y + v1.y; a1.z += u1.z + v1.z; a1.w += u1.w + v1.w;
        a2.x += u2.x + v2.x; a2.y += u2.y + v2.y; a2.z += u2.z + v2.z; a2.w += u2.w + v2.w;
    }
    if (k < deg) {
        int d0 = g_bucket[k * NN + i];
        const float4* r0 = (const float4*)&g_y12[d0 * 12];
        float4 u0 = r0[0], u1 = r0[1], u2 = r0[2];
        a0.x += u0.x; a0.y += u0.y; a0.z += u0.z; a0.w += u0.w;
        a1.x += u1.x; a1.y += u1.y; a1.z += u1.z; a1.w += u1.w;
        a2.x += u2.x; a2.y += u2.y; a2.z += u2.z; a2.w += u2.w;
    }
    float4* out = (float4*)&g_aggx[i * 12];
    out[0] = a0; out[1] = a1; out[2] = a2;
}

// Node pass (warp/node): z = dis*(agg + y); h1 = relu(z@W1+b1) in regs;
// accumulate mean-sum; hd = dis * (h1.W2[:64] + x.W2[64:75])
__global__ void k_node(const float* __restrict__ W1, const float* __restrict__ b1,
                       const float* __restrict__ W2, int n) {
    int gw = (blockIdx.x * blockDim.x + threadIdx.x) >> 5;
    int lane = threadIdx.x & 31;
    int nwarp = (gridDim.x * blockDim.x) >> 5;

    float w1c0[11], w1c1[11];
#pragma unroll
    for (int d = 0; d < 11; d++) {
        w1c0[d] = __ldg(&W1[d * 64 + lane]);
        w1c1[d] = __ldg(&W1[d * 64 + lane + 32]);
    }
    float bb0 = __ldg(&b1[lane]);
    float bb1 = __ldg(&b1[lane + 32]);
    float w2a = __ldg(&W2[lane]);
    float w2b = __ldg(&W2[lane + 32]);
    float w2x[11];
#pragma unroll
    for (int d = 0; d < 11; d++) w2x[d] = __ldg(&W2[64 + d]);

    float m0 = 0.f, m1 = 0.f;

    for (int i = gw; i < n; i += nwarp) {
        float di = g_dis[i];
        const float4* ar = (const float4*)&g_aggx[i * 12];
        const float4* yr = (const float4*)&g_y12[i * 12];
        const float4* xr = (const float4*)&g_x12[i * 12];
        float4 a0 = ar[0], a1 = ar[1], a2 = ar[2];
        float4 y0 = yr[0], y1 = yr[1], y2 = yr[2];
        float4 x0 = xr[0], x1 = xr[1], x2 = xr[2];

        float z[11];
        z[0]  = di * (a0.x + y0.x);
        z[1]  = di * (a0.y + y0.y);
        z[2]  = di * (a0.z + y0.z);
        z[3]  = di * (a0.w + y0.w);
        z[4]  = di * (a1.x + y1.x);
        z[5]  = di * (a1.y + y1.y);
        z[6]  = di * (a1.z + y1.z);
        z[7]  = di * (a1.w + y1.w);
        z[8]  = di * (a2.x + y2.x);
        z[9]  = di * (a2.y + y2.y);
        z[10] = di * (a2.z + y2.z);

        float acc0 = bb0, acc1 = bb1;
#pragma unroll
        for (int d = 0; d < 11; d++) {
            acc0 = fmaf(z[d], w1c0[d], acc0);
            acc1 = fmaf(z[d], w1c1[d], acc1);
        }
        float h0 = fmaxf(acc0, 0.f);
        float h1 = fmaxf(acc1, 0.f);
        m0 += h0;
        m1 += h1;

        float p = h0 * w2a + h1 * w2b;
#pragma unroll
        for (int off = 16; off; off >>= 1)
            p += __shfl_xor_sync(0xffffffffu, p, off);

        if (lane == 0) {
            float xv[11] = {x0.x, x0.y, x0.z, x0.w, x1.x, x1.y, x1.z, x1.w,
                            x2.x, x2.y, x2.z};
            float xa = 0.f;
#pragma unroll
            for (int d = 0; d < 11; d++) xa = fmaf(xv[d], w2x[d], xa);
            g_hd[i] = di * (p + xa);
        }
    }
    atomicAdd(&g_msum[lane], m0);
    atomicAdd(&g_msum[lane + 32], m1);
}

// Layer-2 edge pass over the sharded compacted lists (~1% of edges total).
__global__ void k_edge2() {
    int sh = blockIdx.x;
    int m = g_shcnt[sh];
    if (m > SHCAP) m = SHCAP;
    for (int i = threadIdx.x; i < m; i += blockDim.x) {
        int2 p = g_e2[sh * SHCAP + i];
        atomicAdd(&g_agg2[p.x], g_hd[p.y]);
    }
}

// Readout: x_mean, v, prob_nothing, logits at ready_idx, softmax. One block.
__global__ void k_final(const int* __restrict__ ridx,
                        const float* __restrict__ b2,
                        const float* __restrict__ Wd, const float* __restrict__ bd,
                        const float* __restrict__ Wv, const float* __restrict__ bv,
                        int k, int n, float* __restrict__ out) {
    __shared__ float s_log[KK + 1];
    __shared__ float s_red[1024];
    __shared__ float s_xm[64];
    __shared__ float s_v, s_pn;
    int t = threadIdx.x;

    if (t < 64) s_xm[t] = g_msum[t] / (float)n;
    __syncthreads();

    if (t == 0) {
        float v = 0.f, pn = 0.f;
        for (int j = 0; j < 64; j++) {
            v = fmaf(s_xm[j], Wv[j], v);
            pn = fmaf(s_xm[j], Wd[j], pn);
        }
        s_v = v + bv[0];
        s_pn = pn + bd[0];
    }
    __syncthreads();

    float bb2 = b2[0];
    for (int i = t; i <= k; i += blockDim.x) {
        float l;
        if (i < k) {
            int r = ridx[i];
            l = g_dis[r] * (g_agg2[r] + g_hd[r]) + bb2;
        } else {
            l = s_pn;
        }
        s_log[i] = l;
    }
    __syncthreads();

    // max reduce
    float m = -1e30f;
    for (int i = t; i <= k; i += blockDim.x) m = fmaxf(m, s_log[i]);
    s_red[t] = m;
    __syncthreads();
    for (int s = 512; s; s >>= 1) {
        if (t < s) s_red[t] = fmaxf(s_red[t], s_red[t + s]);
        __syncthreads();
    }
    float mx = s_red[0];
    __syncthreads();

    // sum reduce
    float sum = 0.f;
    for (int i = t; i <= k; i += blockDim.x) sum += expf(s_log[i] - mx);
    s_red[t] = sum;
    __syncthreads();
    for (int s = 512; s; s >>= 1) {
        if (t < s) s_red[t] += s_red[t + s];
        __syncthreads();
    }
    float inv = 1.0f / s_red[0];

    for (int i = t; i <= k; i += blockDim.x)
        out[i] = expf(s_log[i] - mx) * inv;
    if (t == 0) out[k + 1] = s_v;
}

// ---------------- launch -----------------------------------------------------

extern "C" void kernel_launch(void* const* d_in, const int* in_sizes, int n_in,
                              void* d_out, int out_size) {
    const float* x   = (const float*)d_in[0];
    const int*   ei  = (const int*)d_in[1];
    const int*   rid = (const int*)d_in[2];
    const float* W1  = (const float*)d_in[3];
    const float* b1  = (const float*)d_in[4];
    const float* W2  = (const float*)d_in[5];
    const float* b2  = (const float*)d_in[6];
    const float* Wd  = (const float*)d_in[7];
    const float* bd  = (const float*)d_in[8];
    const float* Wv  = (const float*)d_in[9];
    const float* bv  = (const float*)d_in[10];

    int n = in_sizes[0] / 11;
    int e = in_sizes[1] / 2;
    int k = in_sizes[2];
    if (n > NN) n = NN;
    if (e > EE) e = EE;
    if (k > KK) k = KK;

    const int* src = ei;
    const int* dst = ei + e;
    int e4 = e >> 2;

    k_init<<<2368, 256>>>(x, n);
    k_ready<<<(k + 255) / 256, 256>>>(rid, k);
    k_scatter<<<(e4 + 255) / 256, 256>>>(src, dst, e);
    k_disy<<<(n + 255) / 256, 256>>>(n);
    k_gather<<<(n + 255) / 256, 256>>>(n);
    k_node<<<1480, 256>>>(W1, b1, W2, n);
    k_edge2<<<NSH, 256>>>();
    k_final<<<1, 1024>>>(rid, b2, Wd, bd, Wv, bv, k, n, (float*)d_out);
}

// round 6
// speedup vs baseline: 1.5361x; 1.3969x over previous
#include <cuda_runtime.h>
#include <cuda_bf16.h>
#include <math.h>

// Problem constants (fixed by the dataset)
#define NN 100000
#define EE 3200000
#define KK 1024
#define SLOTS 128          // max degree capacity (deg ~ Poisson(32); P(deg>=128) ~ 0)
#define NSH 64             // shards for layer-2 edge compaction
#define SHCAP 32768        // per-shard capacity

// ---------------- scratch (device globals; no allocation allowed) -----------
__device__ __align__(16) float g_x12[NN * 12];   // x padded to 12 cols
__device__ __align__(16) float g_y12[NN * 12];   // dis[i] * x12 (gather table)
__device__ int   g_cnt1[NN];          // bits 0-23: degree; bit 24: ready flag
__device__ float g_dis[NN];
__device__ float g_hd[NN];            // dis[i] * (x_input[i] @ W2)
__device__ float g_agg2[NN];          // layer-2 aggregation (ready rows only)
__device__ float g_vd[2];             // sums of h1.Wv and h1.Wd over all nodes
__device__ int   g_bucket[NN * SLOTS];// CSR row-major: bucket[node*SLOTS + slot]
__device__ int2  g_e2[NSH * SHCAP];   // compacted (src,dst) pairs with ready src
__device__ int   g_shcnt[NSH];

// ---------------- kernels ---------------------------------------------------

// (1) zero counters
__global__ void k_init_a(int n) {
    int idx = blockIdx.x * blockDim.x + threadIdx.x;
    int stride = gridDim.x * blockDim.x;
    for (int j = idx; j < n; j += stride) {
        g_cnt1[j] = 0;
        g_agg2[j] = 0.f;
    }
    if (idx < NSH) g_shcnt[idx] = 0;
    if (idx < 2) g_vd[idx] = 0.f;
}

// (2) ready flags into bit 24 (after counters are zeroed)
__global__ void k_ready(const int* __restrict__ ridx, int k) {
    int t = blockIdx.x * blockDim.x + threadIdx.x;
    if (t < k) atomicOr(&g_cnt1[ridx[t]], 1 << 24);
}

// (3) pad x -> x12, thread per node
__global__ void k_x12(const float* __restrict__ x, int n) {
    int i = blockIdx.x * blockDim.x + threadIdx.x;
    if (i < n) {
        const float* p = x + i * 11;
        float4* o = (float4*)&g_x12[i * 12];
        o[0] = make_float4(p[0], p[1], p[2], p[3]);
        o[1] = make_float4(p[4], p[5], p[6], p[7]);
        o[2] = make_float4(p[8], p[9], p[10], 0.f);
    }
}

// (4) one atomic per edge: degree count + CSR slot + ready-edge compaction
__device__ __forceinline__ void scat(int s, int d, int sh) {
    int old = atomicAdd(&g_cnt1[s], 1);
    int slot = old & 0xFFFFFF;
    if (slot < SLOTS) g_bucket[s * SLOTS + slot] = d;
    if (old & (1 << 24)) {
        int p = atomicAdd(&g_shcnt[sh], 1);
        if (p < SHCAP) g_e2[sh * SHCAP + p] = make_int2(s, d);
    }
}

__global__ void k_scatter(const int* __restrict__ src, const int* __restrict__ dst, int e) {
    int j4 = blockIdx.x * blockDim.x + threadIdx.x;
    int e4 = e >> 2;
    int sh = blockIdx.x & (NSH - 1);
    if (j4 < e4) {
        int4 s = ((const int4*)src)[j4];
        int4 d = ((const int4*)dst)[j4];
        scat(s.x, d.x, sh);
        scat(s.y, d.y, sh);
        scat(s.z, d.z, sh);
        scat(s.w, d.w, sh);
    }
    if (j4 == 0) {  // tail (e % 4)
        for (int j = e4 << 2; j < e; j++) scat(src[j], dst[j], 0);
    }
}

// (5) dis = rsqrt(deg+1); pre-scaled gather table y12 = dis * x12
__global__ void k_disy(int n) {
    int i = blockIdx.x * blockDim.x + threadIdx.x;
    if (i < n) {
        int deg = g_cnt1[i] & 0xFFFFFF;
        float dis = rsqrtf((float)(deg + 1));
        g_dis[i] = dis;
        const float4* xr = (const float4*)&g_x12[i * 12];
        float4* yr = (float4*)&g_y12[i * 12];
#pragma unroll
        for (int q = 0; q < 3; q++) {
            float4 v = xr[q];
            v.x *= dis; v.y *= dis; v.z *= dis; v.w *= dis;
            yr[q] = v;
        }
    }
}

// (6) FUSED: gather-aggregate + layer-1 MLP + layer-2 projection + readout sums.
// Thread per node; no atomic FP aggregation; h1 never materialized.
__global__ void k_gnode(const float* __restrict__ W1, const float* __restrict__ b1,
                        const float* __restrict__ W2,
                        const float* __restrict__ Wv, const float* __restrict__ Wd,
                        int n) {
    __shared__ float4 sW1[64 * 3];   // W1 transposed: sW1[j*3+q] = col q of row j (pad d=11 -> 0)
    __shared__ float sB1[64], sW2[64], sWv[64], sWd[64], sW2x[12];
    int tid = threadIdx.x;

    for (int idx = tid; idx < 704; idx += blockDim.x) {
        int d = idx >> 6, j = idx & 63;          // W1[d*64 + j]
        ((float*)sW1)[j * 12 + d] = W1[idx];
    }
    for (int j = tid; j < 64; j += blockDim.x) {
        ((float*)sW1)[j * 12 + 11] = 0.f;
        sB1[j] = b1[j];
        sW2[j] = W2[j];
        sWv[j] = Wv[j];
        sWd[j] = Wd[j];
    }
    if (tid < 11) sW2x[tid] = W2[64 + tid];
    __syncthreads();

    int i = blockIdx.x * blockDim.x + tid;
    float pv = 0.f, pd = 0.f;

    if (i < n) {
        int deg = g_cnt1[i] & 0xFFFFFF;
        int dd = deg < SLOTS ? deg : SLOTS;
        const int* bk = &g_bucket[i * SLOTS];

        float4 a0 = make_float4(0.f, 0.f, 0.f, 0.f), a1 = a0, a2 = a0;
        int k = 0;
        for (; k + 4 <= dd; k += 4) {
            int4 d4 = *(const int4*)(bk + k);
            const float4* r0 = (const float4*)&g_y12[d4.x * 12];
            const float4* r1 = (const float4*)&g_y12[d4.y * 12];
            const float4* r2 = (const float4*)&g_y12[d4.z * 12];
            const float4* r3 = (const float4*)&g_y12[d4.w * 12];
            float4 u0 = r0[0], u1 = r0[1], u2 = r0[2];
            float4 v0 = r1[0], v1 = r1[1], v2 = r1[2];
            float4 w0 = r2[0], w1 = r2[1], w2 = r2[2];
            float4 t0 = r3[0], t1 = r3[1], t2 = r3[2];
            a0.x += (u0.x + v0.x) + (w0.x + t0.x);
            a0.y += (u0.y + v0.y) + (w0.y + t0.y);
            a0.z += (u0.z + v0.z) + (w0.z + t0.z);
            a0.w += (u0.w + v0.w) + (w0.w + t0.w);
            a1.x += (u1.x + v1.x) + (w1.x + t1.x);
            a1.y += (u1.y + v1.y) + (w1.y + t1.y);
            a1.z += (u1.z + v1.z) + (w1.z + t1.z);
            a1.w += (u1.w + v1.w) + (w1.w + t1.w);
            a2.x += (u2.x + v2.x) + (w2.x + t2.x);
            a2.y += (u2.y + v2.y) + (w2.y + t2.y);
            a2.z += (u2.z + v2.z) + (w2.z + t2.z);
            a2.w += (u2.w + v2.w) + (w2.w + t2.w);
        }
        for (; k < dd; k++) {
            const float4* r0 = (const float4*)&g_y12[bk[k] * 12];
            float4 u0 = r0[0], u1 = r0[1], u2 = r0[2];
            a0.x += u0.x; a0.y += u0.y; a0.z += u0.z; a0.w += u0.w;
            a1.x += u1.x; a1.y += u1.y; a1.z += u1.z; a1.w += u1.w;
            a2.x += u2.x; a2.y += u2.y; a2.z += u2.z; a2.w += u2.w;
        }

        float di = g_dis[i];
        const float4* yr = (const float4*)&g_y12[i * 12];
        const float4* xr = (const float4*)&g_x12[i * 12];
        float4 y0 = yr[0], y1 = yr[1], y2 = yr[2];
        float4 x0 = xr[0], x1 = xr[1], x2 = xr[2];

        float z[12];
        z[0]  = di * (a0.x + y0.x);
        z[1]  = di * (a0.y + y0.y);
        z[2]  = di * (a0.z + y0.z);
        z[3]  = di * (a0.w + y0.w);
        z[4]  = di * (a1.x + y1.x);
        z[5]  = di * (a1.y + y1.y);
        z[6]  = di * (a1.z + y1.z);
        z[7]  = di * (a1.w + y1.w);
        z[8]  = di * (a2.x + y2.x);
        z[9]  = di * (a2.y + y2.y);
        z[10] = di * (a2.z + y2.z);
        z[11] = 0.f;

        float p2 = 0.f;
#pragma unroll 4
        for (int j = 0; j < 64; j++) {
            float4 w0 = sW1[j * 3], w1 = sW1[j * 3 + 1], w2 = sW1[j * 3 + 2];
            float acc = sB1[j];
            acc = fmaf(z[0], w0.x, acc);
            acc = fmaf(z[1], w0.y, acc);
            acc = fmaf(z[2], w0.z, acc);
            acc = fmaf(z[3], w0.w, acc);
            acc = fmaf(z[4], w1.x, acc);
            acc = fmaf(z[5], w1.y, acc);
            acc = fmaf(z[6], w1.z, acc);
            acc = fmaf(z[7], w1.w, acc);
            acc = fmaf(z[8], w2.x, acc);
            acc = fmaf(z[9], w2.y, acc);
            acc = fmaf(z[10], w2.z, acc);
            float h = fmaxf(acc, 0.f);
            p2 = fmaf(h, sW2[j], p2);
            pv = fmaf(h, sWv[j], pv);
            pd = fmaf(h, sWd[j], pd);
        }

        float xa = 0.f;
        xa = fmaf(x0.x, sW2x[0], xa);
        xa = fmaf(x0.y, sW2x[1], xa);
        xa = fmaf(x0.z, sW2x[2], xa);
        xa = fmaf(x0.w, sW2x[3], xa);
        xa = fmaf(x1.x, sW2x[4], xa);
        xa = fmaf(x1.y, sW2x[5], xa);
        xa = fmaf(x1.z, sW2x[6], xa);
        xa = fmaf(x1.w, sW2x[7], xa);
        xa = fmaf(x2.x, sW2x[8], xa);
        xa = fmaf(x2.y, sW2x[9], xa);
        xa = fmaf(x2.z, sW2x[10], xa);
        g_hd[i] = di * (p2 + xa);
    }

    // warp-reduce the readout sums, one atomic pair per warp
#pragma unroll
    for (int off = 16; off; off >>= 1) {
        pv += __shfl_xor_sync(0xffffffffu, pv, off);
        pd += __shfl_xor_sync(0xffffffffu, pd, off);
    }
    if ((tid & 31) == 0) {
        atomicAdd(&g_vd[0], pv);
        atomicAdd(&g_vd[1], pd);
    }
}

// (7) layer-2 edge pass over sharded compacted lists (~1% of edges)
__global__ void k_edge2() {
    int sh = blockIdx.x;
    int m = g_shcnt[sh];
    if (m > SHCAP) m = SHCAP;
    for (int i = threadIdx.x; i < m; i += blockDim.x) {
        int2 p = g_e2[sh * SHCAP + i];
        atomicAdd(&g_agg2[p.x], g_hd[p.y]);
    }
}

// (8) readout: v, prob_nothing, logits at ready_idx, softmax. One block.
__global__ void k_final(const int* __restrict__ ridx,
                        const float* __restrict__ b2,
                        const float* __restrict__ bd, const float* __restrict__ bv,
                        int k, int n, float* __restrict__ out) {
    __shared__ float s_log[KK + 1];
    __shared__ float s_red[1024];
    __shared__ float s_v, s_pn;
    int t = threadIdx.x;

    if (t == 0) {
        float inv_n = 1.0f / (float)n;
        s_v = g_vd[0] * inv_n + bv[0];
        s_pn = g_vd[1] * inv_n + bd[0];
    }
    __syncthreads();

    float bb2 = b2[0];
    for (int i = t; i <= k; i += blockDim.x) {
        float l;
        if (i < k) {
            int r = ridx[i];
            l = g_dis[r] * (g_agg2[r] + g_hd[r]) + bb2;
        } else {
            l = s_pn;
        }
        s_log[i] = l;
    }
    __syncthreads();

    // max reduce
    float m = -1e30f;
    for (int i = t; i <= k; i += blockDim.x) m = fmaxf(m, s_log[i]);
    s_red[t] = m;
    __syncthreads();
    for (int s = 512; s; s >>= 1) {
        if (t < s) s_red[t] = fmaxf(s_red[t], s_red[t + s]);
        __syncthreads();
    }
    float mx = s_red[0];
    __syncthreads();

    // sum reduce
    float sum = 0.f;
    for (int i = t; i <= k; i += blockDim.x) sum += expf(s_log[i] - mx);
    s_red[t] = sum;
    __syncthreads();
    for (int s = 512; s; s >>= 1) {
        if (t < s) s_red[t] += s_red[t + s];
        __syncthreads();
    }
    float inv = 1.0f / s_red[0];

    for (int i = t; i <= k; i += blockDim.x)
        out[i] = expf(s_log[i] - mx) * inv;
    if (t == 0) out[k + 1] = s_v;
}

// ---------------- launch -----------------------------------------------------

extern "C" void kernel_launch(void* const* d_in, const int* in_sizes, int n_in,
                              void* d_out, int out_size) {
    const float* x   = (const float*)d_in[0];
    const int*   ei  = (const int*)d_in[1];
    const int*   rid = (const int*)d_in[2];
    const float* W1  = (const float*)d_in[3];
    const float* b1  = (const float*)d_in[4];
    const float* W2  = (const float*)d_in[5];
    const float* b2  = (const float*)d_in[6];
    const float* Wd  = (const float*)d_in[7];
    const float* bd  = (const float*)d_in[8];
    const float* Wv  = (const float*)d_in[9];
    const float* bv  = (const float*)d_in[10];

    int n = in_sizes[0] / 11;
    int e = in_sizes[1] / 2;
    int k = in_sizes[2];
    if (n > NN) n = NN;
    if (e > EE) e = EE;
    if (k > KK) k = KK;

    const int* src = ei;
    const int* dst = ei + e;
    int e4 = e >> 2;
    int nb = (n + 255) / 256;

    k_init_a<<<512, 256>>>(n);                        // 1
    k_ready<<<(k + 255) / 256, 256>>>(rid, k);        // 2
    k_x12<<<nb, 256>>>(x, n);                         // 3
    k_scatter<<<(e4 + 255) / 256, 256>>>(src, dst, e);// 4  <-- profiled
    k_disy<<<nb, 256>>>(n);                           // 5
    k_gnode<<<nb, 256>>>(W1, b1, W2, Wv, Wd, n);      // 6
    k_edge2<<<NSH, 256>>>();                          // 7
    k_final<<<1, 1024>>>(rid, b2, bd, bv, k, n, (float*)d_out); // 8
}